// round 8
// baseline (speedup 1.0000x reference)
#include <cuda_runtime.h>
#include <math.h>

// Problem constants
#define Dm   1024
#define Sm   2048
#define Bm   2
#define Hh   16
#define DHh  64
#define ROWS (Bm*Sm)      // 4096
#define NEGM (-1e9f)

// ---------------------------------------------------------------------------
// Scratch (module-load-time allocation; no runtime alloc)
// ---------------------------------------------------------------------------
__device__ float g_xln[ROWS*Dm];
__device__ float g_q  [ROWS*Dm];
__device__ float g_k  [ROWS*Dm];
__device__ float g_v  [ROWS*Dm];
__device__ float g_ctx[ROWS*Dm];
__device__ float g_h  [ROWS*Dm];
__device__ float g_hln[ROWS*Dm];
__device__ float g_r  [ROWS*Dm];
__device__ float g_z  [ROWS*Dm];
__device__ float g_mlp[ROWS*4*Dm];

__device__ __forceinline__ float gelu_f(float x) {
    return 0.5f * x * (1.0f + erff(x * 0.70710678118654752440f));
}

// TF32 input rounding — same conversion cuBLAS/CUTLASS apply for f32 matmuls.
__device__ __forceinline__ float tf32r(float x) {
    float r;
    asm("cvt.rna.tf32.f32 %0, %1;" : "=f"(r) : "f"(x));
    return r;
}

// ---------------------------------------------------------------------------
// LayerNorm over D=1024, one block per row, 256 threads
// ---------------------------------------------------------------------------
__global__ void ln_kernel(const float* __restrict__ in, const float* __restrict__ g,
                          const float* __restrict__ bb, float* __restrict__ out)
{
    __shared__ float xs[Dm];
    __shared__ float red[8];
    int row = blockIdx.x, tid = threadIdx.x;
    const float* ip = in + (size_t)row * Dm;

    float s = 0.f;
    #pragma unroll
    for (int i = tid; i < Dm; i += 256) { float v = ip[i]; xs[i] = v; s += v; }
    #pragma unroll
    for (int o = 16; o > 0; o >>= 1) s += __shfl_xor_sync(0xffffffffu, s, o);
    if ((tid & 31) == 0) red[tid >> 5] = s;
    __syncthreads();
    float tot = 0.f;
    #pragma unroll
    for (int i = 0; i < 8; i++) tot += red[i];
    float mu = tot * (1.0f / Dm);

    float vs = 0.f;
    #pragma unroll
    for (int i = tid; i < Dm; i += 256) { float d = xs[i] - mu; vs += d * d; }
    #pragma unroll
    for (int o = 16; o > 0; o >>= 1) vs += __shfl_xor_sync(0xffffffffu, vs, o);
    __syncthreads();
    if ((tid & 31) == 0) red[tid >> 5] = vs;
    __syncthreads();
    tot = 0.f;
    #pragma unroll
    for (int i = 0; i < 8; i++) tot += red[i];
    float inv = rsqrtf(tot * (1.0f / Dm) + 1e-5f);

    float* op = out + (size_t)row * Dm;
    #pragma unroll
    for (int i = tid; i < Dm; i += 256)
        op[i] = (xs[i] - mu) * inv * g[i] + bb[i];
}

// Embedding gather (tok_emb[ids] + pos_emb) fused with LayerNorm
__global__ void embed_ln_kernel(const int* __restrict__ ids, const float* __restrict__ tok,
                                const float* __restrict__ pos, const float* __restrict__ g,
                                const float* __restrict__ bb, float* __restrict__ out)
{
    __shared__ float xs[Dm];
    __shared__ float red[8];
    int row = blockIdx.x, tid = threadIdx.x;
    int spos = row % Sm;
    int id = ids[row];
    const float* tp = tok + (size_t)id * Dm;
    const float* pp = pos + (size_t)spos * Dm;

    float s = 0.f;
    #pragma unroll
    for (int i = tid; i < Dm; i += 256) { float v = tp[i] + pp[i]; xs[i] = v; s += v; }
    #pragma unroll
    for (int o = 16; o > 0; o >>= 1) s += __shfl_xor_sync(0xffffffffu, s, o);
    if ((tid & 31) == 0) red[tid >> 5] = s;
    __syncthreads();
    float tot = 0.f;
    #pragma unroll
    for (int i = 0; i < 8; i++) tot += red[i];
    float mu = tot * (1.0f / Dm);

    float vs = 0.f;
    #pragma unroll
    for (int i = tid; i < Dm; i += 256) { float d = xs[i] - mu; vs += d * d; }
    #pragma unroll
    for (int o = 16; o > 0; o >>= 1) vs += __shfl_xor_sync(0xffffffffu, vs, o);
    __syncthreads();
    if ((tid & 31) == 0) red[tid >> 5] = vs;
    __syncthreads();
    tot = 0.f;
    #pragma unroll
    for (int i = 0; i < 8; i++) tot += red[i];
    float inv = rsqrtf(tot * (1.0f / Dm) + 1e-5f);

    float* op = out + (size_t)row * Dm;
    #pragma unroll
    for (int i = tid; i < Dm; i += 256)
        op[i] = (xs[i] - mu) * inv * g[i] + bb[i];
}

// ---------------------------------------------------------------------------
// GEMM with TF32-rounded inputs, fp32 accumulate:
// C[M,N] = tf32(A)[M,K] @ tf32(W)[K,N] + bias (+residual) (+GELU)
// BM=BN=128, BK=16, 256 threads, 8x8 per thread
// ---------------------------------------------------------------------------
#define GBM 128
#define GBN 128
#define GBK 16

template<bool RES, bool GELU>
__global__ void __launch_bounds__(256)
gemm_kernel(const float* __restrict__ A, const float* __restrict__ W,
            const float* __restrict__ bias, const float* __restrict__ Rsrc,
            float* __restrict__ C, int M, int N, int K)
{
    __shared__ float As[GBK][GBM];
    __shared__ float Bs[GBK][GBN];

    int tid = threadIdx.x;
    int bm = blockIdx.y * GBM, bn = blockIdx.x * GBN;
    int tx = tid & 15, ty = tid >> 4;

    float acc[8][8];
    #pragma unroll
    for (int i = 0; i < 8; i++)
        #pragma unroll
        for (int j = 0; j < 8; j++) acc[i][j] = 0.f;

    for (int k0 = 0; k0 < K; k0 += GBK) {
        // Load A tile (128 rows x 16 k), TF32-round, store transposed As[k][m]
        #pragma unroll
        for (int it = 0; it < 2; it++) {
            int idx = tid + it * 256;          // float4 index 0..511
            int r  = idx >> 2;                 // 0..127
            int c  = (idx & 3) << 2;           // 0,4,8,12
            float4 va = *(const float4*)(A + (size_t)(bm + r) * K + k0 + c);
            As[c + 0][r] = tf32r(va.x); As[c + 1][r] = tf32r(va.y);
            As[c + 2][r] = tf32r(va.z); As[c + 3][r] = tf32r(va.w);
        }
        // Load B tile (16 k x 128 cols), TF32-round
        #pragma unroll
        for (int it = 0; it < 2; it++) {
            int idx = tid + it * 256;
            int r  = idx >> 5;                 // 0..15
            int c  = (idx & 31) << 2;          // 0..124
            float4 vb = *(const float4*)(W + (size_t)(k0 + r) * N + bn + c);
            Bs[r][c + 0] = tf32r(vb.x); Bs[r][c + 1] = tf32r(vb.y);
            Bs[r][c + 2] = tf32r(vb.z); Bs[r][c + 3] = tf32r(vb.w);
        }
        __syncthreads();

        #pragma unroll
        for (int kk = 0; kk < GBK; kk++) {
            float a[8], bfr[8];
            float4 a0 = *(const float4*)&As[kk][ty * 8];
            float4 a1 = *(const float4*)&As[kk][ty * 8 + 4];
            a[0]=a0.x; a[1]=a0.y; a[2]=a0.z; a[3]=a0.w;
            a[4]=a1.x; a[5]=a1.y; a[6]=a1.z; a[7]=a1.w;
            float4 b0 = *(const float4*)&Bs[kk][tx * 8];
            float4 b1 = *(const float4*)&Bs[kk][tx * 8 + 4];
            bfr[0]=b0.x; bfr[1]=b0.y; bfr[2]=b0.z; bfr[3]=b0.w;
            bfr[4]=b1.x; bfr[5]=b1.y; bfr[6]=b1.z; bfr[7]=b1.w;
            #pragma unroll
            for (int i = 0; i < 8; i++)
                #pragma unroll
                for (int j = 0; j < 8; j++)
                    acc[i][j] += a[i] * bfr[j];
        }
        __syncthreads();
    }

    // Epilogue (fp32, matches reference elementwise ops)
    #pragma unroll
    for (int i = 0; i < 8; i++) {
        int row = bm + ty * 8 + i;
        #pragma unroll
        for (int j = 0; j < 8; j++) {
            int col = bn + tx * 8 + j;
            float v = acc[i][j] + bias[col];
            if (RES)  v += Rsrc[(size_t)row * N + col];
            if (GELU) v = gelu_f(v);
            C[(size_t)row * N + col] = v;
        }
    }
}

// ---------------------------------------------------------------------------
// Two-pass attention, TF32-matched numerics. Layout [B, S, H, DH].
// Block: 128 threads = 128 query rows, one (b,h). Key tiles of 32 in smem.
// Pass 1: row max m and denominator l (online). Pass 2: recompute logits,
// accumulate o += tf32(exp(s-m)/l) * tf32(V).
// Scale 1/8 folded into q (exact power-of-two, commutes with TF32 rounding).
// ---------------------------------------------------------------------------
template<bool CAUSAL>
__global__ void __launch_bounds__(128)
attn_kernel(const float* __restrict__ Q, const float* __restrict__ Kp,
            const float* __restrict__ Vp, const int* __restrict__ ids,
            float* __restrict__ O)
{
    __shared__ float Ks[32][64];
    __shared__ float Vs[32][64];
    __shared__ float Ps[32][128];
    __shared__ int   ids_s[32];

    int b = blockIdx.z, h = blockIdx.y;
    int q = blockIdx.x * 128 + threadIdx.x;

    float qreg[64];
    const float* qptr = Q + (((size_t)b * Sm + q) * Hh + h) * DHh;
    #pragma unroll
    for (int d = 0; d < 64; d++) qreg[d] = tf32r(qptr[d]) * 0.125f;

    int ktiles = CAUSAL ? (blockIdx.x * 4 + 4) : (Sm / 32);

    // ---------------- Pass 1: m and l ----------------
    float m = -1e30f, l = 0.f;
    for (int kt = 0; kt < ktiles; kt++) {
        int k0 = kt * 32;
        __syncthreads();
        #pragma unroll
        for (int i = threadIdx.x; i < 32 * 16; i += 128) {
            int r  = i >> 4;
            int c4 = (i & 15) << 2;
            size_t base = (((size_t)b * Sm + k0 + r) * Hh + h) * DHh + c4;
            float4 vk = *(const float4*)(Kp + base);
            Ks[r][c4+0] = tf32r(vk.x); Ks[r][c4+1] = tf32r(vk.y);
            Ks[r][c4+2] = tf32r(vk.z); Ks[r][c4+3] = tf32r(vk.w);
        }
        if (threadIdx.x < 32) ids_s[threadIdx.x] = ids[b * Sm + k0 + threadIdx.x];
        __syncthreads();

        float tmax = -1e30f;
        for (int j = 0; j < 32; j++) {
            int kj = k0 + j;
            float dot = 0.f;
            #pragma unroll
            for (int d = 0; d < 64; d++) dot += qreg[d] * Ks[j][d];
            if (CAUSAL && kj > q) dot += NEGM;
            if (ids_s[j] == 0)    dot += NEGM;
            Ps[j][threadIdx.x] = dot;
            tmax = fmaxf(tmax, dot);
        }
        float mnew = fmaxf(m, tmax);
        l *= expf(m - mnew);
        for (int j = 0; j < 32; j++)
            l += expf(Ps[j][threadIdx.x] - mnew);
        m = mnew;
    }
    float linv = 1.0f / l;

    // ---------------- Pass 2: output ----------------
    float o[64];
    #pragma unroll
    for (int d = 0; d < 64; d++) o[d] = 0.f;

    for (int kt = 0; kt < ktiles; kt++) {
        int k0 = kt * 32;
        __syncthreads();
        #pragma unroll
        for (int i = threadIdx.x; i < 32 * 16; i += 128) {
            int r  = i >> 4;
            int c4 = (i & 15) << 2;
            size_t base = (((size_t)b * Sm + k0 + r) * Hh + h) * DHh + c4;
            float4 vk = *(const float4*)(Kp + base);
            Ks[r][c4+0] = tf32r(vk.x); Ks[r][c4+1] = tf32r(vk.y);
            Ks[r][c4+2] = tf32r(vk.z); Ks[r][c4+3] = tf32r(vk.w);
            float4 vv = *(const float4*)(Vp + base);
            Vs[r][c4+0] = tf32r(vv.x); Vs[r][c4+1] = tf32r(vv.y);
            Vs[r][c4+2] = tf32r(vv.z); Vs[r][c4+3] = tf32r(vv.w);
        }
        if (threadIdx.x < 32) ids_s[threadIdx.x] = ids[b * Sm + k0 + threadIdx.x];
        __syncthreads();

        for (int j = 0; j < 32; j++) {
            int kj = k0 + j;
            float dot = 0.f;
            #pragma unroll
            for (int d = 0; d < 64; d++) dot += qreg[d] * Ks[j][d];
            if (CAUSAL && kj > q) dot += NEGM;
            if (ids_s[j] == 0)    dot += NEGM;
            float p = tf32r(expf(dot - m) * linv);
            #pragma unroll
            for (int d = 0; d < 64; d++) o[d] += p * Vs[j][d];
        }
    }

    float* optr = O + (((size_t)b * Sm + q) * Hh + h) * DHh;
    #pragma unroll
    for (int d = 0; d < 64; d++) optr[d] = o[d];
}

// ---------------------------------------------------------------------------
// Launch
// ---------------------------------------------------------------------------
extern "C" void kernel_launch(void* const* d_in, const int* in_sizes, int n_in,
                              void* d_out, int out_size)
{
    const float* input_embedding = (const float*)d_in[0];
    const int*   input_ids       = (const int*)  d_in[1];
    const int*   target_ids      = (const int*)  d_in[2];
    const float* tok_emb = (const float*)d_in[3];
    const float* pos_emb = (const float*)d_in[4];
    const float* ln1_g = (const float*)d_in[5],  *ln1_b = (const float*)d_in[6];
    const float* q1_w  = (const float*)d_in[7],  *q1_b  = (const float*)d_in[8];
    const float* k1_w  = (const float*)d_in[9],  *k1_b  = (const float*)d_in[10];
    const float* v1_w  = (const float*)d_in[11], *v1_b  = (const float*)d_in[12];
    const float* out1_w= (const float*)d_in[13], *out1_b= (const float*)d_in[14];
    const float* ln2_g = (const float*)d_in[15], *ln2_b = (const float*)d_in[16];
    const float* q2_w  = (const float*)d_in[17], *q2_b  = (const float*)d_in[18];
    const float* k2_w  = (const float*)d_in[19], *k2_b  = (const float*)d_in[20];
    const float* v2_w  = (const float*)d_in[21], *v2_b  = (const float*)d_in[22];
    const float* out2_w= (const float*)d_in[23], *out2_b= (const float*)d_in[24];
    const float* ln3_g = (const float*)d_in[25], *ln3_b = (const float*)d_in[26];
    const float* mlp_w1= (const float*)d_in[27], *mlp_b1= (const float*)d_in[28];
    const float* mlp_w2= (const float*)d_in[29], *mlp_b2= (const float*)d_in[30];
    float* out = (float*)d_out;

    float *xln,*q,*k,*v,*ctx,*h,*hln,*r,*z,*mlp;
    cudaGetSymbolAddress((void**)&xln, g_xln);
    cudaGetSymbolAddress((void**)&q,   g_q);
    cudaGetSymbolAddress((void**)&k,   g_k);
    cudaGetSymbolAddress((void**)&v,   g_v);
    cudaGetSymbolAddress((void**)&ctx, g_ctx);
    cudaGetSymbolAddress((void**)&h,   g_h);
    cudaGetSymbolAddress((void**)&hln, g_hln);
    cudaGetSymbolAddress((void**)&r,   g_r);
    cudaGetSymbolAddress((void**)&z,   g_z);
    cudaGetSymbolAddress((void**)&mlp, g_mlp);

    dim3 gP(Dm / GBN, ROWS / GBM);      // projections: N=1024
    dim3 gU(4 * Dm / GBN, ROWS / GBM);  // MLP up: N=4096
    dim3 gA(Sm / 128, Hh, Bm);          // attention

    // x = LN1(tok_emb[target_ids] + pos_emb)
    embed_ln_kernel<<<ROWS, 256>>>(target_ids, tok_emb, pos_emb, ln1_g, ln1_b, xln);

    // Self-attention QKV
    gemm_kernel<false,false><<<gP, 256>>>(xln, q1_w, q1_b, nullptr, q, ROWS, Dm, Dm);
    gemm_kernel<false,false><<<gP, 256>>>(xln, k1_w, k1_b, nullptr, k, ROWS, Dm, Dm);
    gemm_kernel<false,false><<<gP, 256>>>(xln, v1_w, v1_b, nullptr, v, ROWS, Dm, Dm);
    attn_kernel<true><<<gA, 128>>>(q, k, v, target_ids, ctx);
    // h = xln + ctx @ out1_w + out1_b
    gemm_kernel<true,false><<<gP, 256>>>(ctx, out1_w, out1_b, xln, h, ROWS, Dm, Dm);

    // Cross-attention. NOTE: reference reassigns h = LN2(h); residual is hln.
    ln_kernel<<<ROWS, 256>>>(h, ln2_g, ln2_b, hln);
    gemm_kernel<false,false><<<gP, 256>>>(hln, q2_w, q2_b, nullptr, q, ROWS, Dm, Dm);
    gemm_kernel<false,false><<<gP, 256>>>(input_embedding, k2_w, k2_b, nullptr, k, ROWS, Dm, Dm);
    gemm_kernel<false,false><<<gP, 256>>>(input_embedding, v2_w, v2_b, nullptr, v, ROWS, Dm, Dm);
    attn_kernel<false><<<gA, 128>>>(q, k, v, input_ids, ctx);
    // r = LN2(h) + ctx @ out2_w + out2_b   (residual = hln, FIXED)
    gemm_kernel<true,false><<<gP, 256>>>(ctx, out2_w, out2_b, hln, r, ROWS, Dm, Dm);

    // MLP
    ln_kernel<<<ROWS, 256>>>(r, ln3_g, ln3_b, z);
    gemm_kernel<false,true><<<gU, 256>>>(z, mlp_w1, mlp_b1, nullptr, mlp, ROWS, 4 * Dm, Dm);
    gemm_kernel<true,false><<<gP, 256>>>(mlp, mlp_w2, mlp_b2, r, out, ROWS, Dm, 4 * Dm);
}

// round 9
// speedup vs baseline: 1.4709x; 1.4709x over previous
#include <cuda_runtime.h>
#include <math.h>
#include <stdint.h>

// Problem constants
#define Dm   1024
#define Sm   2048
#define Bm   2
#define Hh   16
#define DHh  64
#define ROWS (Bm*Sm)      // 4096
#define NEGM (-1e9f)

// ---------------------------------------------------------------------------
// Scratch (module-load-time allocation; no runtime alloc)
// ---------------------------------------------------------------------------
__device__ float g_xln[ROWS*Dm];
__device__ float g_q  [ROWS*Dm];
__device__ float g_k  [ROWS*Dm];
__device__ float g_v  [ROWS*Dm];
__device__ float g_ctx[ROWS*Dm];
__device__ float g_h  [ROWS*Dm];
__device__ float g_hln[ROWS*Dm];
__device__ float g_r  [ROWS*Dm];
__device__ float g_z  [ROWS*Dm];
__device__ float g_mlp[ROWS*4*Dm];

__device__ __forceinline__ float gelu_f(float x) {
    return 0.5f * x * (1.0f + erff(x * 0.70710678118654752440f));
}

// TF32 input rounding — same conversion cuBLAS/CUTLASS apply for f32 matmuls.
__device__ __forceinline__ float tf32r(float x) {
    float r;
    asm("cvt.rna.tf32.f32 %0, %1;" : "=f"(r) : "f"(x));
    return r;
}

// ---------------------------------------------------------------------------
// LayerNorm over D=1024, one block per row, 256 threads
// ---------------------------------------------------------------------------
__global__ void ln_kernel(const float* __restrict__ in, const float* __restrict__ g,
                          const float* __restrict__ bb, float* __restrict__ out)
{
    __shared__ float xs[Dm];
    __shared__ float red[8];
    int row = blockIdx.x, tid = threadIdx.x;
    const float* ip = in + (size_t)row * Dm;

    float s = 0.f;
    #pragma unroll
    for (int i = tid; i < Dm; i += 256) { float v = ip[i]; xs[i] = v; s += v; }
    #pragma unroll
    for (int o = 16; o > 0; o >>= 1) s += __shfl_xor_sync(0xffffffffu, s, o);
    if ((tid & 31) == 0) red[tid >> 5] = s;
    __syncthreads();
    float tot = 0.f;
    #pragma unroll
    for (int i = 0; i < 8; i++) tot += red[i];
    float mu = tot * (1.0f / Dm);

    float vs = 0.f;
    #pragma unroll
    for (int i = tid; i < Dm; i += 256) { float d = xs[i] - mu; vs += d * d; }
    #pragma unroll
    for (int o = 16; o > 0; o >>= 1) vs += __shfl_xor_sync(0xffffffffu, vs, o);
    __syncthreads();
    if ((tid & 31) == 0) red[tid >> 5] = vs;
    __syncthreads();
    tot = 0.f;
    #pragma unroll
    for (int i = 0; i < 8; i++) tot += red[i];
    float inv = rsqrtf(tot * (1.0f / Dm) + 1e-5f);

    float* op = out + (size_t)row * Dm;
    #pragma unroll
    for (int i = tid; i < Dm; i += 256)
        op[i] = (xs[i] - mu) * inv * g[i] + bb[i];
}

// Embedding gather (tok_emb[ids] + pos_emb) fused with LayerNorm
__global__ void embed_ln_kernel(const int* __restrict__ ids, const float* __restrict__ tok,
                                const float* __restrict__ pos, const float* __restrict__ g,
                                const float* __restrict__ bb, float* __restrict__ out)
{
    __shared__ float xs[Dm];
    __shared__ float red[8];
    int row = blockIdx.x, tid = threadIdx.x;
    int spos = row % Sm;
    int id = ids[row];
    const float* tp = tok + (size_t)id * Dm;
    const float* pp = pos + (size_t)spos * Dm;

    float s = 0.f;
    #pragma unroll
    for (int i = tid; i < Dm; i += 256) { float v = tp[i] + pp[i]; xs[i] = v; s += v; }
    #pragma unroll
    for (int o = 16; o > 0; o >>= 1) s += __shfl_xor_sync(0xffffffffu, s, o);
    if ((tid & 31) == 0) red[tid >> 5] = s;
    __syncthreads();
    float tot = 0.f;
    #pragma unroll
    for (int i = 0; i < 8; i++) tot += red[i];
    float mu = tot * (1.0f / Dm);

    float vs = 0.f;
    #pragma unroll
    for (int i = tid; i < Dm; i += 256) { float d = xs[i] - mu; vs += d * d; }
    #pragma unroll
    for (int o = 16; o > 0; o >>= 1) vs += __shfl_xor_sync(0xffffffffu, vs, o);
    __syncthreads();
    if ((tid & 31) == 0) red[tid >> 5] = vs;
    __syncthreads();
    tot = 0.f;
    #pragma unroll
    for (int i = 0; i < 8; i++) tot += red[i];
    float inv = rsqrtf(tot * (1.0f / Dm) + 1e-5f);

    float* op = out + (size_t)row * Dm;
    #pragma unroll
    for (int i = tid; i < Dm; i += 256)
        op[i] = (xs[i] - mu) * inv * g[i] + bb[i];
}

// ---------------------------------------------------------------------------
// Tensor-core GEMM (mma.sync m16n8k8 tf32, fp32 accumulate):
// C[M,N] = tf32(A)[M,K] @ tf32(W)[K,N] + bias (+residual) (+GELU)
// 128x128x32 block tile, 256 threads = 8 warps (2x4), warp tile 64x32.
// A smem: [m][k] stride 40, k XOR-swizzled by (row&4) -> conflict-free frags.
// B smem: [k][n] stride 136 -> conflict-free frags.
// ---------------------------------------------------------------------------
#define ASTR 40
#define BSTR 136

__device__ __forceinline__ void mma_tf32(float* c, uint32_t a0, uint32_t a1,
                                         uint32_t a2, uint32_t a3,
                                         uint32_t b0, uint32_t b1)
{
    asm volatile(
        "mma.sync.aligned.m16n8k8.row.col.f32.tf32.tf32.f32 "
        "{%0,%1,%2,%3}, {%4,%5,%6,%7}, {%8,%9}, {%0,%1,%2,%3};"
        : "+f"(c[0]), "+f"(c[1]), "+f"(c[2]), "+f"(c[3])
        : "r"(a0), "r"(a1), "r"(a2), "r"(a3), "r"(b0), "r"(b1));
}

template<bool RES, bool GELU>
__global__ void __launch_bounds__(256)
gemm_tc(const float* __restrict__ A, const float* __restrict__ W,
        const float* __restrict__ bias, const float* __restrict__ Rsrc,
        float* __restrict__ C, int M, int N, int K)
{
    __shared__ float As[128 * ASTR];
    __shared__ float Bs[32 * BSTR];

    int tid = threadIdx.x, lane = tid & 31, warp = tid >> 5;
    int wm = warp >> 2, wn = warp & 3;       // 2 x 4 warp grid
    int bm = blockIdx.y * 128, bn = blockIdx.x * 128;
    int g = lane >> 2, t4 = lane & 3;
    int swz = (g & 4);                       // A k-swizzle for this thread's frag rows

    float acc[4][4][4];
    #pragma unroll
    for (int i = 0; i < 4; i++)
        #pragma unroll
        for (int j = 0; j < 4; j++)
            #pragma unroll
            for (int c = 0; c < 4; c++) acc[i][j][c] = 0.f;

    for (int k0 = 0; k0 < K; k0 += 32) {
        // A tile: 128x32, tf32-rounded, swizzled store
        #pragma unroll
        for (int it = 0; it < 4; it++) {
            int idx = tid + it * 256;            // 0..1023 float4 slots
            int r = idx >> 3, c = (idx & 7) << 2;
            float4 v = *(const float4*)(A + (size_t)(bm + r) * K + k0 + c);
            int cs = c ^ (r & 4);
            *(float4*)&As[r * ASTR + cs] =
                make_float4(tf32r(v.x), tf32r(v.y), tf32r(v.z), tf32r(v.w));
        }
        // B tile: 32x128
        #pragma unroll
        for (int it = 0; it < 4; it++) {
            int idx = tid + it * 256;
            int r = idx >> 5, c = (idx & 31) << 2;
            float4 v = *(const float4*)(W + (size_t)(k0 + r) * N + bn + c);
            *(float4*)&Bs[r * BSTR + c] =
                make_float4(tf32r(v.x), tf32r(v.y), tf32r(v.z), tf32r(v.w));
        }
        __syncthreads();

        #pragma unroll
        for (int ks = 0; ks < 4; ks++) {
            int kb = ks * 8;
            int kA  = (kb + t4) ^ swz;
            int kA4 = (kb + t4 + 4) ^ swz;
            uint32_t a[4][4], b[4][2];
            #pragma unroll
            for (int mt = 0; mt < 4; mt++) {
                int r0 = wm * 64 + mt * 16 + g;
                int r1 = r0 + 8;
                a[mt][0] = __float_as_uint(As[r0 * ASTR + kA ]);
                a[mt][1] = __float_as_uint(As[r1 * ASTR + kA ]);
                a[mt][2] = __float_as_uint(As[r0 * ASTR + kA4]);
                a[mt][3] = __float_as_uint(As[r1 * ASTR + kA4]);
            }
            #pragma unroll
            for (int nt = 0; nt < 4; nt++) {
                int col = wn * 32 + nt * 8 + g;
                b[nt][0] = __float_as_uint(Bs[(kb + t4    ) * BSTR + col]);
                b[nt][1] = __float_as_uint(Bs[(kb + t4 + 4) * BSTR + col]);
            }
            #pragma unroll
            for (int mt = 0; mt < 4; mt++)
                #pragma unroll
                for (int nt = 0; nt < 4; nt++)
                    mma_tf32(acc[mt][nt], a[mt][0], a[mt][1], a[mt][2], a[mt][3],
                             b[nt][0], b[nt][1]);
        }
        __syncthreads();
    }

    // Epilogue
    #pragma unroll
    for (int mt = 0; mt < 4; mt++) {
        #pragma unroll
        for (int nt = 0; nt < 4; nt++) {
            int col = bn + wn * 32 + nt * 8 + t4 * 2;
            float b0 = bias[col], b1 = bias[col + 1];
            #pragma unroll
            for (int half = 0; half < 2; half++) {
                int row = bm + wm * 64 + mt * 16 + g + half * 8;
                float v0 = acc[mt][nt][half * 2 + 0] + b0;
                float v1 = acc[mt][nt][half * 2 + 1] + b1;
                if (RES) {
                    v0 += Rsrc[(size_t)row * N + col];
                    v1 += Rsrc[(size_t)row * N + col + 1];
                }
                if (GELU) { v0 = gelu_f(v0); v1 = gelu_f(v1); }
                *(float2*)(C + (size_t)row * N + col) = make_float2(v0, v1);
            }
        }
    }
}

// ---------------------------------------------------------------------------
// Two-pass attention, TF32-matched numerics. Layout [B, S, H, DH].
// Block: 128 threads = 128 query rows, one (b,h). Key tiles of 32 in smem.
// Inner loops use float4 smem reads (4x fewer LDS issues).
// ---------------------------------------------------------------------------
template<bool CAUSAL>
__global__ void __launch_bounds__(128)
attn_kernel(const float* __restrict__ Q, const float* __restrict__ Kp,
            const float* __restrict__ Vp, const int* __restrict__ ids,
            float* __restrict__ O)
{
    __shared__ float Ks[32][64];
    __shared__ float Vs[32][64];
    __shared__ float Ps[32][128];
    __shared__ int   ids_s[32];

    int b = blockIdx.z, h = blockIdx.y;
    int q = blockIdx.x * 128 + threadIdx.x;

    float qreg[64];
    const float* qptr = Q + (((size_t)b * Sm + q) * Hh + h) * DHh;
    #pragma unroll
    for (int d = 0; d < 64; d++) qreg[d] = tf32r(qptr[d]) * 0.125f;

    int ktiles = CAUSAL ? (blockIdx.x * 4 + 4) : (Sm / 32);

    // ---------------- Pass 1: m and l ----------------
    float m = -1e30f, l = 0.f;
    for (int kt = 0; kt < ktiles; kt++) {
        int k0 = kt * 32;
        __syncthreads();
        #pragma unroll
        for (int i = threadIdx.x; i < 32 * 16; i += 128) {
            int r  = i >> 4;
            int c4 = (i & 15) << 2;
            size_t base = (((size_t)b * Sm + k0 + r) * Hh + h) * DHh + c4;
            float4 vk = *(const float4*)(Kp + base);
            Ks[r][c4+0] = tf32r(vk.x); Ks[r][c4+1] = tf32r(vk.y);
            Ks[r][c4+2] = tf32r(vk.z); Ks[r][c4+3] = tf32r(vk.w);
        }
        if (threadIdx.x < 32) ids_s[threadIdx.x] = ids[b * Sm + k0 + threadIdx.x];
        __syncthreads();

        float tmax = -1e30f;
        for (int j = 0; j < 32; j++) {
            int kj = k0 + j;
            const float4* kr = (const float4*)&Ks[j][0];
            float dot = 0.f;
            #pragma unroll
            for (int d4 = 0; d4 < 16; d4++) {
                float4 kv = kr[d4];
                dot += qreg[d4*4+0]*kv.x + qreg[d4*4+1]*kv.y
                     + qreg[d4*4+2]*kv.z + qreg[d4*4+3]*kv.w;
            }
            if (CAUSAL && kj > q) dot += NEGM;
            if (ids_s[j] == 0)    dot += NEGM;
            Ps[j][threadIdx.x] = dot;
            tmax = fmaxf(tmax, dot);
        }
        float mnew = fmaxf(m, tmax);
        l *= expf(m - mnew);
        for (int j = 0; j < 32; j++)
            l += expf(Ps[j][threadIdx.x] - mnew);
        m = mnew;
    }
    float linv = 1.0f / l;

    // ---------------- Pass 2: output ----------------
    float o[64];
    #pragma unroll
    for (int d = 0; d < 64; d++) o[d] = 0.f;

    for (int kt = 0; kt < ktiles; kt++) {
        int k0 = kt * 32;
        __syncthreads();
        #pragma unroll
        for (int i = threadIdx.x; i < 32 * 16; i += 128) {
            int r  = i >> 4;
            int c4 = (i & 15) << 2;
            size_t base = (((size_t)b * Sm + k0 + r) * Hh + h) * DHh + c4;
            float4 vk = *(const float4*)(Kp + base);
            Ks[r][c4+0] = tf32r(vk.x); Ks[r][c4+1] = tf32r(vk.y);
            Ks[r][c4+2] = tf32r(vk.z); Ks[r][c4+3] = tf32r(vk.w);
            float4 vv = *(const float4*)(Vp + base);
            Vs[r][c4+0] = tf32r(vv.x); Vs[r][c4+1] = tf32r(vv.y);
            Vs[r][c4+2] = tf32r(vv.z); Vs[r][c4+3] = tf32r(vv.w);
        }
        if (threadIdx.x < 32) ids_s[threadIdx.x] = ids[b * Sm + k0 + threadIdx.x];
        __syncthreads();

        for (int j = 0; j < 32; j++) {
            int kj = k0 + j;
            const float4* kr = (const float4*)&Ks[j][0];
            float dot = 0.f;
            #pragma unroll
            for (int d4 = 0; d4 < 16; d4++) {
                float4 kv = kr[d4];
                dot += qreg[d4*4+0]*kv.x + qreg[d4*4+1]*kv.y
                     + qreg[d4*4+2]*kv.z + qreg[d4*4+3]*kv.w;
            }
            if (CAUSAL && kj > q) dot += NEGM;
            if (ids_s[j] == 0)    dot += NEGM;
            float p = tf32r(expf(dot - m) * linv);
            const float4* vr = (const float4*)&Vs[j][0];
            #pragma unroll
            for (int d4 = 0; d4 < 16; d4++) {
                float4 vv = vr[d4];
                o[d4*4+0] += p * vv.x; o[d4*4+1] += p * vv.y;
                o[d4*4+2] += p * vv.z; o[d4*4+3] += p * vv.w;
            }
        }
    }

    float* optr = O + (((size_t)b * Sm + q) * Hh + h) * DHh;
    #pragma unroll
    for (int d = 0; d < 64; d++) optr[d] = o[d];
}

// ---------------------------------------------------------------------------
// Launch
// ---------------------------------------------------------------------------
extern "C" void kernel_launch(void* const* d_in, const int* in_sizes, int n_in,
                              void* d_out, int out_size)
{
    const float* input_embedding = (const float*)d_in[0];
    const int*   input_ids       = (const int*)  d_in[1];
    const int*   target_ids      = (const int*)  d_in[2];
    const float* tok_emb = (const float*)d_in[3];
    const float* pos_emb = (const float*)d_in[4];
    const float* ln1_g = (const float*)d_in[5],  *ln1_b = (const float*)d_in[6];
    const float* q1_w  = (const float*)d_in[7],  *q1_b  = (const float*)d_in[8];
    const float* k1_w  = (const float*)d_in[9],  *k1_b  = (const float*)d_in[10];
    const float* v1_w  = (const float*)d_in[11], *v1_b  = (const float*)d_in[12];
    const float* out1_w= (const float*)d_in[13], *out1_b= (const float*)d_in[14];
    const float* ln2_g = (const float*)d_in[15], *ln2_b = (const float*)d_in[16];
    const float* q2_w  = (const float*)d_in[17], *q2_b  = (const float*)d_in[18];
    const float* k2_w  = (const float*)d_in[19], *k2_b  = (const float*)d_in[20];
    const float* v2_w  = (const float*)d_in[21], *v2_b  = (const float*)d_in[22];
    const float* out2_w= (const float*)d_in[23], *out2_b= (const float*)d_in[24];
    const float* ln3_g = (const float*)d_in[25], *ln3_b = (const float*)d_in[26];
    const float* mlp_w1= (const float*)d_in[27], *mlp_b1= (const float*)d_in[28];
    const float* mlp_w2= (const float*)d_in[29], *mlp_b2= (const float*)d_in[30];
    float* out = (float*)d_out;

    float *xln,*q,*k,*v,*ctx,*h,*hln,*r,*z,*mlp;
    cudaGetSymbolAddress((void**)&xln, g_xln);
    cudaGetSymbolAddress((void**)&q,   g_q);
    cudaGetSymbolAddress((void**)&k,   g_k);
    cudaGetSymbolAddress((void**)&v,   g_v);
    cudaGetSymbolAddress((void**)&ctx, g_ctx);
    cudaGetSymbolAddress((void**)&h,   g_h);
    cudaGetSymbolAddress((void**)&hln, g_hln);
    cudaGetSymbolAddress((void**)&r,   g_r);
    cudaGetSymbolAddress((void**)&z,   g_z);
    cudaGetSymbolAddress((void**)&mlp, g_mlp);

    dim3 gP(Dm / 128, ROWS / 128);      // projections: N=1024
    dim3 gU(4 * Dm / 128, ROWS / 128);  // MLP up: N=4096
    dim3 gA(Sm / 128, Hh, Bm);          // attention

    // x = LN1(tok_emb[target_ids] + pos_emb)
    embed_ln_kernel<<<ROWS, 256>>>(target_ids, tok_emb, pos_emb, ln1_g, ln1_b, xln);

    // Self-attention QKV
    gemm_tc<false,false><<<gP, 256>>>(xln, q1_w, q1_b, nullptr, q, ROWS, Dm, Dm);
    gemm_tc<false,false><<<gP, 256>>>(xln, k1_w, k1_b, nullptr, k, ROWS, Dm, Dm);
    gemm_tc<false,false><<<gP, 256>>>(xln, v1_w, v1_b, nullptr, v, ROWS, Dm, Dm);
    attn_kernel<true><<<gA, 128>>>(q, k, v, target_ids, ctx);
    // h = xln + ctx @ out1_w + out1_b
    gemm_tc<true,false><<<gP, 256>>>(ctx, out1_w, out1_b, xln, h, ROWS, Dm, Dm);

    // Cross-attention. Reference reassigns h = LN2(h); residual is hln.
    ln_kernel<<<ROWS, 256>>>(h, ln2_g, ln2_b, hln);
    gemm_tc<false,false><<<gP, 256>>>(hln, q2_w, q2_b, nullptr, q, ROWS, Dm, Dm);
    gemm_tc<false,false><<<gP, 256>>>(input_embedding, k2_w, k2_b, nullptr, k, ROWS, Dm, Dm);
    gemm_tc<false,false><<<gP, 256>>>(input_embedding, v2_w, v2_b, nullptr, v, ROWS, Dm, Dm);
    attn_kernel<false><<<gA, 128>>>(q, k, v, input_ids, ctx);
    // r = LN2(h) + ctx @ out2_w + out2_b
    gemm_tc<true,false><<<gP, 256>>>(ctx, out2_w, out2_b, hln, r, ROWS, Dm, Dm);

    // MLP
    ln_kernel<<<ROWS, 256>>>(r, ln3_g, ln3_b, z);
    gemm_tc<false,true><<<gU, 256>>>(z, mlp_w1, mlp_b1, nullptr, mlp, ROWS, 4 * Dm, Dm);
    gemm_tc<true,false><<<gP, 256>>>(mlp, mlp_w2, mlp_b2, r, out, ROWS, Dm, 4 * Dm);
}

// round 11
// speedup vs baseline: 3.9940x; 2.7152x over previous
#include <cuda_runtime.h>
#include <math.h>
#include <stdint.h>

// Problem constants
#define Dm   1024
#define Sm   2048
#define Bm   2
#define Hh   16
#define DHh  64
#define ROWS (Bm*Sm)      // 4096
#define NEGM (-1e9f)

// ---------------------------------------------------------------------------
// Scratch (module-load-time allocation; no runtime alloc)
// ---------------------------------------------------------------------------
__device__ float g_xln[ROWS*Dm];
__device__ float g_q  [ROWS*Dm];
__device__ float g_k  [ROWS*Dm];
__device__ float g_v  [ROWS*Dm];
__device__ float g_ctx[ROWS*Dm];
__device__ float g_h  [ROWS*Dm];
__device__ float g_hln[ROWS*Dm];
__device__ float g_r  [ROWS*Dm];
__device__ float g_z  [ROWS*Dm];
__device__ float g_mlp[ROWS*4*Dm];

__device__ __forceinline__ float gelu_f(float x) {
    return 0.5f * x * (1.0f + erff(x * 0.70710678118654752440f));
}

// TF32 input rounding — same conversion cuBLAS/CUTLASS apply for f32 matmuls.
__device__ __forceinline__ float tf32r(float x) {
    float r;
    asm("cvt.rna.tf32.f32 %0, %1;" : "=f"(r) : "f"(x));
    return r;
}

// ---------------------------------------------------------------------------
// LayerNorm over D=1024, one block per row, 256 threads
// ---------------------------------------------------------------------------
__global__ void ln_kernel(const float* __restrict__ in, const float* __restrict__ g,
                          const float* __restrict__ bb, float* __restrict__ out)
{
    __shared__ float xs[Dm];
    __shared__ float red[8];
    int row = blockIdx.x, tid = threadIdx.x;
    const float* ip = in + (size_t)row * Dm;

    float s = 0.f;
    #pragma unroll
    for (int i = tid; i < Dm; i += 256) { float v = ip[i]; xs[i] = v; s += v; }
    #pragma unroll
    for (int o = 16; o > 0; o >>= 1) s += __shfl_xor_sync(0xffffffffu, s, o);
    if ((tid & 31) == 0) red[tid >> 5] = s;
    __syncthreads();
    float tot = 0.f;
    #pragma unroll
    for (int i = 0; i < 8; i++) tot += red[i];
    float mu = tot * (1.0f / Dm);

    float vs = 0.f;
    #pragma unroll
    for (int i = tid; i < Dm; i += 256) { float d = xs[i] - mu; vs += d * d; }
    #pragma unroll
    for (int o = 16; o > 0; o >>= 1) vs += __shfl_xor_sync(0xffffffffu, vs, o);
    __syncthreads();
    if ((tid & 31) == 0) red[tid >> 5] = vs;
    __syncthreads();
    tot = 0.f;
    #pragma unroll
    for (int i = 0; i < 8; i++) tot += red[i];
    float inv = rsqrtf(tot * (1.0f / Dm) + 1e-5f);

    float* op = out + (size_t)row * Dm;
    #pragma unroll
    for (int i = tid; i < Dm; i += 256)
        op[i] = (xs[i] - mu) * inv * g[i] + bb[i];
}

// Embedding gather (tok_emb[ids] + pos_emb) fused with LayerNorm
__global__ void embed_ln_kernel(const int* __restrict__ ids, const float* __restrict__ tok,
                                const float* __restrict__ pos, const float* __restrict__ g,
                                const float* __restrict__ bb, float* __restrict__ out)
{
    __shared__ float xs[Dm];
    __shared__ float red[8];
    int row = blockIdx.x, tid = threadIdx.x;
    int spos = row % Sm;
    int id = ids[row];
    const float* tp = tok + (size_t)id * Dm;
    const float* pp = pos + (size_t)spos * Dm;

    float s = 0.f;
    #pragma unroll
    for (int i = tid; i < Dm; i += 256) { float v = tp[i] + pp[i]; xs[i] = v; s += v; }
    #pragma unroll
    for (int o = 16; o > 0; o >>= 1) s += __shfl_xor_sync(0xffffffffu, s, o);
    if ((tid & 31) == 0) red[tid >> 5] = s;
    __syncthreads();
    float tot = 0.f;
    #pragma unroll
    for (int i = 0; i < 8; i++) tot += red[i];
    float mu = tot * (1.0f / Dm);

    float vs = 0.f;
    #pragma unroll
    for (int i = tid; i < Dm; i += 256) { float d = xs[i] - mu; vs += d * d; }
    #pragma unroll
    for (int o = 16; o > 0; o >>= 1) vs += __shfl_xor_sync(0xffffffffu, vs, o);
    __syncthreads();
    if ((tid & 31) == 0) red[tid >> 5] = vs;
    __syncthreads();
    tot = 0.f;
    #pragma unroll
    for (int i = 0; i < 8; i++) tot += red[i];
    float inv = rsqrtf(tot * (1.0f / Dm) + 1e-5f);

    float* op = out + (size_t)row * Dm;
    #pragma unroll
    for (int i = tid; i < Dm; i += 256)
        op[i] = (xs[i] - mu) * inv * g[i] + bb[i];
}

// ---------------------------------------------------------------------------
// mma.sync m16n8k8 tf32 helper
// ---------------------------------------------------------------------------
__device__ __forceinline__ void mma_tf32(float* c, uint32_t a0, uint32_t a1,
                                         uint32_t a2, uint32_t a3,
                                         uint32_t b0, uint32_t b1)
{
    asm volatile(
        "mma.sync.aligned.m16n8k8.row.col.f32.tf32.tf32.f32 "
        "{%0,%1,%2,%3}, {%4,%5,%6,%7}, {%8,%9}, {%0,%1,%2,%3};"
        : "+f"(c[0]), "+f"(c[1]), "+f"(c[2]), "+f"(c[3])
        : "r"(a0), "r"(a1), "r"(a2), "r"(a3), "r"(b0), "r"(b1));
}

// ---------------------------------------------------------------------------
// Tensor-core GEMM (unchanged from R9)
// ---------------------------------------------------------------------------
#define ASTR 40
#define BSTR 136

template<bool RES, bool GELU>
__global__ void __launch_bounds__(256)
gemm_tc(const float* __restrict__ A, const float* __restrict__ W,
        const float* __restrict__ bias, const float* __restrict__ Rsrc,
        float* __restrict__ C, int M, int N, int K)
{
    __shared__ float As[128 * ASTR];
    __shared__ float Bs[32 * BSTR];

    int tid = threadIdx.x, lane = tid & 31, warp = tid >> 5;
    int wm = warp >> 2, wn = warp & 3;
    int bm = blockIdx.y * 128, bn = blockIdx.x * 128;
    int g = lane >> 2, t4 = lane & 3;
    int swz = (g & 4);

    float acc[4][4][4];
    #pragma unroll
    for (int i = 0; i < 4; i++)
        #pragma unroll
        for (int j = 0; j < 4; j++)
            #pragma unroll
            for (int c = 0; c < 4; c++) acc[i][j][c] = 0.f;

    for (int k0 = 0; k0 < K; k0 += 32) {
        #pragma unroll
        for (int it = 0; it < 4; it++) {
            int idx = tid + it * 256;
            int r = idx >> 3, c = (idx & 7) << 2;
            float4 v = *(const float4*)(A + (size_t)(bm + r) * K + k0 + c);
            int cs = c ^ (r & 4);
            *(float4*)&As[r * ASTR + cs] =
                make_float4(tf32r(v.x), tf32r(v.y), tf32r(v.z), tf32r(v.w));
        }
        #pragma unroll
        for (int it = 0; it < 4; it++) {
            int idx = tid + it * 256;
            int r = idx >> 5, c = (idx & 31) << 2;
            float4 v = *(const float4*)(W + (size_t)(k0 + r) * N + bn + c);
            *(float4*)&Bs[r * BSTR + c] =
                make_float4(tf32r(v.x), tf32r(v.y), tf32r(v.z), tf32r(v.w));
        }
        __syncthreads();

        #pragma unroll
        for (int ks = 0; ks < 4; ks++) {
            int kb = ks * 8;
            int kA  = (kb + t4) ^ swz;
            int kA4 = (kb + t4 + 4) ^ swz;
            uint32_t a[4][4], b[4][2];
            #pragma unroll
            for (int mt = 0; mt < 4; mt++) {
                int r0 = wm * 64 + mt * 16 + g;
                int r1 = r0 + 8;
                a[mt][0] = __float_as_uint(As[r0 * ASTR + kA ]);
                a[mt][1] = __float_as_uint(As[r1 * ASTR + kA ]);
                a[mt][2] = __float_as_uint(As[r0 * ASTR + kA4]);
                a[mt][3] = __float_as_uint(As[r1 * ASTR + kA4]);
            }
            #pragma unroll
            for (int nt = 0; nt < 4; nt++) {
                int col = wn * 32 + nt * 8 + g;
                b[nt][0] = __float_as_uint(Bs[(kb + t4    ) * BSTR + col]);
                b[nt][1] = __float_as_uint(Bs[(kb + t4 + 4) * BSTR + col]);
            }
            #pragma unroll
            for (int mt = 0; mt < 4; mt++)
                #pragma unroll
                for (int nt = 0; nt < 4; nt++)
                    mma_tf32(acc[mt][nt], a[mt][0], a[mt][1], a[mt][2], a[mt][3],
                             b[nt][0], b[nt][1]);
        }
        __syncthreads();
    }

    #pragma unroll
    for (int mt = 0; mt < 4; mt++) {
        #pragma unroll
        for (int nt = 0; nt < 4; nt++) {
            int col = bn + wn * 32 + nt * 8 + t4 * 2;
            float b0 = bias[col], b1 = bias[col + 1];
            #pragma unroll
            for (int half = 0; half < 2; half++) {
                int row = bm + wm * 64 + mt * 16 + g + half * 8;
                float v0 = acc[mt][nt][half * 2 + 0] + b0;
                float v1 = acc[mt][nt][half * 2 + 1] + b1;
                if (RES) {
                    v0 += Rsrc[(size_t)row * N + col];
                    v1 += Rsrc[(size_t)row * N + col + 1];
                }
                if (GELU) { v0 = gelu_f(v0); v1 = gelu_f(v1); }
                *(float2*)(C + (size_t)row * N + col) = make_float2(v0, v1);
            }
        }
    }
}

// ---------------------------------------------------------------------------
// Tensor-core flash attention. Layout [B, S, H, DH].
// Block = 128 threads (4 warps), 64 q rows per block, one (b,h).
// Key tiles of 32. QK^T and PV both via mma m16n8k8 tf32.
// Warp w owns q rows [w*16, w*16+16). Online softmax on fragments.
// Smem strides: Qs/Ks 68 (QK frag conflict-free), Vs 72 (PV conflict-free),
// Ps 36 (A-frag reload conflict-free).
// ---------------------------------------------------------------------------
#define KSTR 68
#define VSTR 72
#define PSTR 36

template<bool CAUSAL>
__global__ void __launch_bounds__(128)
attn_tc(const float* __restrict__ Qp, const float* __restrict__ Kp,
        const float* __restrict__ Vp, const int* __restrict__ ids,
        float* __restrict__ O)
{
    __shared__ float Qs[64 * KSTR];
    __shared__ float Ks[32 * KSTR];
    __shared__ float Vs[32 * VSTR];
    __shared__ float Ps[64 * PSTR];
    __shared__ int   ids_s[32];

    int b = blockIdx.z, h = blockIdx.y, qb = blockIdx.x;
    int tid = threadIdx.x, lane = tid & 31, warp = tid >> 5;
    int g = lane >> 2, t4 = lane & 3;

    // Stage Q tile (64 x 64), tf32-rounded, pre-scaled by 1/8
    #pragma unroll
    for (int i = tid; i < 64 * 16; i += 128) {
        int r = i >> 4, c4 = (i & 15) << 2;
        size_t base = (((size_t)b * Sm + qb * 64 + r) * Hh + h) * DHh + c4;
        float4 v = *(const float4*)(Qp + base);
        Qs[r*KSTR + c4+0] = tf32r(v.x) * 0.125f;
        Qs[r*KSTR + c4+1] = tf32r(v.y) * 0.125f;
        Qs[r*KSTR + c4+2] = tf32r(v.z) * 0.125f;
        Qs[r*KSTR + c4+3] = tf32r(v.w) * 0.125f;
    }
    __syncthreads();

    // Q fragments in registers: 8 k-chunks x 4 regs
    uint32_t qa[8][4];
    int rw0 = warp * 16 + g, rw1 = rw0 + 8;
    #pragma unroll
    for (int kc = 0; kc < 8; kc++) {
        qa[kc][0] = __float_as_uint(Qs[rw0*KSTR + kc*8 + t4    ]);
        qa[kc][1] = __float_as_uint(Qs[rw1*KSTR + kc*8 + t4    ]);
        qa[kc][2] = __float_as_uint(Qs[rw0*KSTR + kc*8 + t4 + 4]);
        qa[kc][3] = __float_as_uint(Qs[rw1*KSTR + kc*8 + t4 + 4]);
    }

    float m0 = -1e30f, m1 = -1e30f, l0 = 0.f, l1 = 0.f;
    float o[8][4];
    #pragma unroll
    for (int nt = 0; nt < 8; nt++)
        #pragma unroll
        for (int c = 0; c < 4; c++) o[nt][c] = 0.f;

    int qrow0 = qb * 64 + warp * 16 + g;   // global q row (c0,c1)
    int qrow1 = qrow0 + 8;                 // global q row (c2,c3)
    int ktiles = CAUSAL ? (qb * 2 + 2) : (Sm / 32);

    for (int kt = 0; kt < ktiles; kt++) {
        int k0 = kt * 32;
        __syncthreads();
        // Load K,V tiles (32 x 64), tf32-rounded
        #pragma unroll
        for (int i = tid; i < 32 * 16; i += 128) {
            int r = i >> 4, c4 = (i & 15) << 2;
            size_t base = (((size_t)b * Sm + k0 + r) * Hh + h) * DHh + c4;
            float4 vk = *(const float4*)(Kp + base);
            Ks[r*KSTR + c4+0] = tf32r(vk.x); Ks[r*KSTR + c4+1] = tf32r(vk.y);
            Ks[r*KSTR + c4+2] = tf32r(vk.z); Ks[r*KSTR + c4+3] = tf32r(vk.w);
            float4 vv = *(const float4*)(Vp + base);
            Vs[r*VSTR + c4+0] = tf32r(vv.x); Vs[r*VSTR + c4+1] = tf32r(vv.y);
            Vs[r*VSTR + c4+2] = tf32r(vv.z); Vs[r*VSTR + c4+3] = tf32r(vv.w);
        }
        if (tid < 32) ids_s[tid] = ids[b * Sm + k0 + tid];
        __syncthreads();

        // S = Q K^T : 4 n-tiles of 8 keys
        float s[4][4];
        #pragma unroll
        for (int nt = 0; nt < 4; nt++) {
            s[nt][0] = s[nt][1] = s[nt][2] = s[nt][3] = 0.f;
            const float* kb = &Ks[(nt*8 + g) * KSTR];
            #pragma unroll
            for (int kc = 0; kc < 8; kc++) {
                uint32_t b0 = __float_as_uint(kb[kc*8 + t4    ]);
                uint32_t b1 = __float_as_uint(kb[kc*8 + t4 + 4]);
                mma_tf32(s[nt], qa[kc][0], qa[kc][1], qa[kc][2], qa[kc][3], b0, b1);
            }
        }

        // Masks (additive, exactly like reference: pad and causal add independently)
        bool diag = CAUSAL && (k0 + 31 > qb * 64);
        #pragma unroll
        for (int nt = 0; nt < 4; nt++) {
            int lk0 = nt*8 + 2*t4, lk1 = lk0 + 1;
            float pad0 = (ids_s[lk0] == 0) ? NEGM : 0.f;
            float pad1 = (ids_s[lk1] == 0) ? NEGM : 0.f;
            s[nt][0] += pad0; s[nt][1] += pad1;
            s[nt][2] += pad0; s[nt][3] += pad1;
            if (diag) {
                int key0 = k0 + lk0, key1 = k0 + lk1;
                if (key0 > qrow0) s[nt][0] += NEGM;
                if (key1 > qrow0) s[nt][1] += NEGM;
                if (key0 > qrow1) s[nt][2] += NEGM;
                if (key1 > qrow1) s[nt][3] += NEGM;
            }
        }

        // Row max over this tile (reduce over quad: lanes sharing g)
        float tm0 = -1e30f, tm1 = -1e30f;
        #pragma unroll
        for (int nt = 0; nt < 4; nt++) {
            tm0 = fmaxf(tm0, fmaxf(s[nt][0], s[nt][1]));
            tm1 = fmaxf(tm1, fmaxf(s[nt][2], s[nt][3]));
        }
        tm0 = fmaxf(tm0, __shfl_xor_sync(0xffffffffu, tm0, 1));
        tm0 = fmaxf(tm0, __shfl_xor_sync(0xffffffffu, tm0, 2));
        tm1 = fmaxf(tm1, __shfl_xor_sync(0xffffffffu, tm1, 1));
        tm1 = fmaxf(tm1, __shfl_xor_sync(0xffffffffu, tm1, 2));

        float mn0 = fmaxf(m0, tm0), mn1 = fmaxf(m1, tm1);
        float cr0 = expf(m0 - mn0), cr1 = expf(m1 - mn1);
        l0 *= cr0; l1 *= cr1;
        #pragma unroll
        for (int nt = 0; nt < 8; nt++) {
            o[nt][0] *= cr0; o[nt][1] *= cr0;
            o[nt][2] *= cr1; o[nt][3] *= cr1;
        }

        // p = exp(s - m), tf32-rounded into Ps; row sums
        float ps0 = 0.f, ps1 = 0.f;
        #pragma unroll
        for (int nt = 0; nt < 4; nt++) {
            float p0 = expf(s[nt][0] - mn0);
            float p1 = expf(s[nt][1] - mn0);
            float p2 = expf(s[nt][2] - mn1);
            float p3 = expf(s[nt][3] - mn1);
            ps0 += p0 + p1; ps1 += p2 + p3;
            *(float2*)&Ps[rw0*PSTR + nt*8 + 2*t4] = make_float2(tf32r(p0), tf32r(p1));
            *(float2*)&Ps[rw1*PSTR + nt*8 + 2*t4] = make_float2(tf32r(p2), tf32r(p3));
        }
        ps0 += __shfl_xor_sync(0xffffffffu, ps0, 1);
        ps0 += __shfl_xor_sync(0xffffffffu, ps0, 2);
        ps1 += __shfl_xor_sync(0xffffffffu, ps1, 1);
        ps1 += __shfl_xor_sync(0xffffffffu, ps1, 2);
        l0 += ps0; l1 += ps1;
        m0 = mn0; m1 = mn1;
        __syncwarp();  // Ps rows are per-warp: warp-local producer->consumer

        // O += P V : 4 key chunks x 8 d-tiles
        #pragma unroll
        for (int kc = 0; kc < 4; kc++) {
            uint32_t a0 = __float_as_uint(Ps[rw0*PSTR + kc*8 + t4    ]);
            uint32_t a1 = __float_as_uint(Ps[rw1*PSTR + kc*8 + t4    ]);
            uint32_t a2 = __float_as_uint(Ps[rw0*PSTR + kc*8 + t4 + 4]);
            uint32_t a3 = __float_as_uint(Ps[rw1*PSTR + kc*8 + t4 + 4]);
            const float* v0p = &Vs[(kc*8 + t4    ) * VSTR];
            const float* v1p = &Vs[(kc*8 + t4 + 4) * VSTR];
            #pragma unroll
            for (int nt = 0; nt < 8; nt++) {
                uint32_t b0 = __float_as_uint(v0p[nt*8 + g]);
                uint32_t b1 = __float_as_uint(v1p[nt*8 + g]);
                mma_tf32(o[nt], a0, a1, a2, a3, b0, b1);
            }
        }
    }

    // Finalize: divide by l, write out
    float i0 = 1.0f / l0, i1 = 1.0f / l1;
    size_t ob0 = (((size_t)b * Sm + qrow0) * Hh + h) * DHh;
    size_t ob1 = (((size_t)b * Sm + qrow1) * Hh + h) * DHh;
    #pragma unroll
    for (int nt = 0; nt < 8; nt++) {
        int col = nt*8 + 2*t4;
        *(float2*)(O + ob0 + col) = make_float2(o[nt][0] * i0, o[nt][1] * i0);
        *(float2*)(O + ob1 + col) = make_float2(o[nt][2] * i1, o[nt][3] * i1);
    }
}

// ---------------------------------------------------------------------------
// Launch
// ---------------------------------------------------------------------------
extern "C" void kernel_launch(void* const* d_in, const int* in_sizes, int n_in,
                              void* d_out, int out_size)
{
    const float* input_embedding = (const float*)d_in[0];
    const int*   input_ids       = (const int*)  d_in[1];
    const int*   target_ids      = (const int*)  d_in[2];
    const float* tok_emb = (const float*)d_in[3];
    const float* pos_emb = (const float*)d_in[4];
    const float* ln1_g = (const float*)d_in[5],  *ln1_b = (const float*)d_in[6];
    const float* q1_w  = (const float*)d_in[7],  *q1_b  = (const float*)d_in[8];
    const float* k1_w  = (const float*)d_in[9],  *k1_b  = (const float*)d_in[10];
    const float* v1_w  = (const float*)d_in[11], *v1_b  = (const float*)d_in[12];
    const float* out1_w= (const float*)d_in[13], *out1_b= (const float*)d_in[14];
    const float* ln2_g = (const float*)d_in[15], *ln2_b = (const float*)d_in[16];
    const float* q2_w  = (const float*)d_in[17], *q2_b  = (const float*)d_in[18];
    const float* k2_w  = (const float*)d_in[19], *k2_b  = (const float*)d_in[20];
    const float* v2_w  = (const float*)d_in[21], *v2_b  = (const float*)d_in[22];
    const float* out2_w= (const float*)d_in[23], *out2_b= (const float*)d_in[24];
    const float* ln3_g = (const float*)d_in[25], *ln3_b = (const float*)d_in[26];
    const float* mlp_w1= (const float*)d_in[27], *mlp_b1= (const float*)d_in[28];
    const float* mlp_w2= (const float*)d_in[29], *mlp_b2= (const float*)d_in[30];
    float* out = (float*)d_out;

    float *xln,*q,*k,*v,*ctx,*h,*hln,*r,*z,*mlp;
    cudaGetSymbolAddress((void**)&xln, g_xln);
    cudaGetSymbolAddress((void**)&q,   g_q);
    cudaGetSymbolAddress((void**)&k,   g_k);
    cudaGetSymbolAddress((void**)&v,   g_v);
    cudaGetSymbolAddress((void**)&ctx, g_ctx);
    cudaGetSymbolAddress((void**)&h,   g_h);
    cudaGetSymbolAddress((void**)&hln, g_hln);
    cudaGetSymbolAddress((void**)&r,   g_r);
    cudaGetSymbolAddress((void**)&z,   g_z);
    cudaGetSymbolAddress((void**)&mlp, g_mlp);

    dim3 gP(Dm / 128, ROWS / 128);      // projections: N=1024
    dim3 gU(4 * Dm / 128, ROWS / 128);  // MLP up: N=4096
    dim3 gA(Sm / 64, Hh, Bm);           // attention: 64 q rows per block

    // x = LN1(tok_emb[target_ids] + pos_emb)
    embed_ln_kernel<<<ROWS, 256>>>(target_ids, tok_emb, pos_emb, ln1_g, ln1_b, xln);

    // Self-attention QKV
    gemm_tc<false,false><<<gP, 256>>>(xln, q1_w, q1_b, nullptr, q, ROWS, Dm, Dm);
    gemm_tc<false,false><<<gP, 256>>>(xln, k1_w, k1_b, nullptr, k, ROWS, Dm, Dm);
    gemm_tc<false,false><<<gP, 256>>>(xln, v1_w, v1_b, nullptr, v, ROWS, Dm, Dm);
    attn_tc<true><<<gA, 128>>>(q, k, v, target_ids, ctx);
    // h = xln + ctx @ out1_w + out1_b
    gemm_tc<true,false><<<gP, 256>>>(ctx, out1_w, out1_b, xln, h, ROWS, Dm, Dm);

    // Cross-attention. Reference reassigns h = LN2(h); residual is hln.
    ln_kernel<<<ROWS, 256>>>(h, ln2_g, ln2_b, hln);
    gemm_tc<false,false><<<gP, 256>>>(hln, q2_w, q2_b, nullptr, q, ROWS, Dm, Dm);
    gemm_tc<false,false><<<gP, 256>>>(input_embedding, k2_w, k2_b, nullptr, k, ROWS, Dm, Dm);
    gemm_tc<false,false><<<gP, 256>>>(input_embedding, v2_w, v2_b, nullptr, v, ROWS, Dm, Dm);
    attn_tc<false><<<gA, 128>>>(q, k, v, input_ids, ctx);
    // r = LN2(h) + ctx @ out2_w + out2_b
    gemm_tc<true,false><<<gP, 256>>>(ctx, out2_w, out2_b, hln, r, ROWS, Dm, Dm);

    // MLP
    ln_kernel<<<ROWS, 256>>>(r, ln3_g, ln3_b, z);
    gemm_tc<false,true><<<gU, 256>>>(z, mlp_w1, mlp_b1, nullptr, mlp, ROWS, 4 * Dm, Dm);
    gemm_tc<true,false><<<gP, 256>>>(mlp, mlp_w2, mlp_b2, r, out, ROWS, Dm, 4 * Dm);
}

// round 16
// speedup vs baseline: 4.3799x; 1.0966x over previous
#include <cuda_runtime.h>
#include <math.h>
#include <stdint.h>

// Problem constants
#define Dm   1024
#define Sm   2048
#define Bm   2
#define Hh   16
#define DHh  64
#define ROWS (Bm*Sm)      // 4096
#define NEGM (-1e9f)

// ---------------------------------------------------------------------------
// Scratch (module-load-time allocation; no runtime alloc)
// ---------------------------------------------------------------------------
__device__ float g_xln [ROWS*Dm];
__device__ float g_xlnr[ROWS*Dm];
__device__ float g_q   [ROWS*Dm];
__device__ float g_k   [ROWS*Dm];
__device__ float g_v   [ROWS*Dm];
__device__ float g_ctx [ROWS*Dm];
__device__ float g_h   [ROWS*Dm];
__device__ float g_hln [ROWS*Dm];
__device__ float g_hlnr[ROWS*Dm];
__device__ float g_r   [ROWS*Dm];
__device__ float g_z   [ROWS*Dm];
__device__ float g_zr  [ROWS*Dm];
__device__ float g_mlp [ROWS*4*Dm];
__device__ float g_wr  [16*1024*1024];   // rounded weights
__device__ float g_ier [ROWS*Dm];        // rounded input_embedding

// offsets (floats) into g_wr
#define W_Q1   (0*1024*1024)
#define W_K1   (1*1024*1024)
#define W_V1   (2*1024*1024)
#define W_O1   (3*1024*1024)
#define W_Q2   (4*1024*1024)
#define W_K2   (5*1024*1024)
#define W_V2   (6*1024*1024)
#define W_O2   (7*1024*1024)
#define W_M1   (8*1024*1024)
#define W_M2   (12*1024*1024)

__device__ __forceinline__ float gelu_f(float x) {
    return 0.5f * x * (1.0f + erff(x * 0.70710678118654752440f));
}

// TF32 input rounding — same conversion cuBLAS/CUTLASS apply for f32 matmuls.
__device__ __forceinline__ float tf32r(float x) {
    float r;
    asm("cvt.rna.tf32.f32 %0, %1;" : "=f"(r) : "f"(x));
    return r;
}

// ---------------------------------------------------------------------------
// Elementwise TF32 rounding copy (for weights / input_embedding)
// ---------------------------------------------------------------------------
__global__ void round_copy(const float* __restrict__ in, float* __restrict__ out, int n4)
{
    int i = blockIdx.x * 256 + threadIdx.x;
    if (i < n4) {
        float4 v = ((const float4*)in)[i];
        ((float4*)out)[i] = make_float4(tf32r(v.x), tf32r(v.y), tf32r(v.z), tf32r(v.w));
    }
}

// ---------------------------------------------------------------------------
// LayerNorm over D=1024, one block per row, 256 threads.
// Writes full-precision out and tf32-rounded out_r (for GEMM A inputs).
// ---------------------------------------------------------------------------
__global__ void ln_kernel(const float* __restrict__ in, const float* __restrict__ g,
                          const float* __restrict__ bb, float* __restrict__ out,
                          float* __restrict__ out_r)
{
    __shared__ float xs[Dm];
    __shared__ float red[8];
    int row = blockIdx.x, tid = threadIdx.x;
    const float* ip = in + (size_t)row * Dm;

    float s = 0.f;
    #pragma unroll
    for (int i = tid; i < Dm; i += 256) { float v = ip[i]; xs[i] = v; s += v; }
    #pragma unroll
    for (int o = 16; o > 0; o >>= 1) s += __shfl_xor_sync(0xffffffffu, s, o);
    if ((tid & 31) == 0) red[tid >> 5] = s;
    __syncthreads();
    float tot = 0.f;
    #pragma unroll
    for (int i = 0; i < 8; i++) tot += red[i];
    float mu = tot * (1.0f / Dm);

    float vs = 0.f;
    #pragma unroll
    for (int i = tid; i < Dm; i += 256) { float d = xs[i] - mu; vs += d * d; }
    #pragma unroll
    for (int o = 16; o > 0; o >>= 1) vs += __shfl_xor_sync(0xffffffffu, vs, o);
    __syncthreads();
    if ((tid & 31) == 0) red[tid >> 5] = vs;
    __syncthreads();
    tot = 0.f;
    #pragma unroll
    for (int i = 0; i < 8; i++) tot += red[i];
    float inv = rsqrtf(tot * (1.0f / Dm) + 1e-5f);

    float* op  = out   + (size_t)row * Dm;
    float* opr = out_r + (size_t)row * Dm;
    #pragma unroll
    for (int i = tid; i < Dm; i += 256) {
        float y = (xs[i] - mu) * inv * g[i] + bb[i];
        op[i]  = y;
        opr[i] = tf32r(y);
    }
}

// Embedding gather (tok_emb[ids] + pos_emb) fused with LayerNorm, dual output
__global__ void embed_ln_kernel(const int* __restrict__ ids, const float* __restrict__ tok,
                                const float* __restrict__ pos, const float* __restrict__ g,
                                const float* __restrict__ bb, float* __restrict__ out,
                                float* __restrict__ out_r)
{
    __shared__ float xs[Dm];
    __shared__ float red[8];
    int row = blockIdx.x, tid = threadIdx.x;
    int spos = row % Sm;
    int id = ids[row];
    const float* tp = tok + (size_t)id * Dm;
    const float* pp = pos + (size_t)spos * Dm;

    float s = 0.f;
    #pragma unroll
    for (int i = tid; i < Dm; i += 256) { float v = tp[i] + pp[i]; xs[i] = v; s += v; }
    #pragma unroll
    for (int o = 16; o > 0; o >>= 1) s += __shfl_xor_sync(0xffffffffu, s, o);
    if ((tid & 31) == 0) red[tid >> 5] = s;
    __syncthreads();
    float tot = 0.f;
    #pragma unroll
    for (int i = 0; i < 8; i++) tot += red[i];
    float mu = tot * (1.0f / Dm);

    float vs = 0.f;
    #pragma unroll
    for (int i = tid; i < Dm; i += 256) { float d = xs[i] - mu; vs += d * d; }
    #pragma unroll
    for (int o = 16; o > 0; o >>= 1) vs += __shfl_xor_sync(0xffffffffu, vs, o);
    __syncthreads();
    if ((tid & 31) == 0) red[tid >> 5] = vs;
    __syncthreads();
    tot = 0.f;
    #pragma unroll
    for (int i = 0; i < 8; i++) tot += red[i];
    float inv = rsqrtf(tot * (1.0f / Dm) + 1e-5f);

    float* op  = out   + (size_t)row * Dm;
    float* opr = out_r + (size_t)row * Dm;
    #pragma unroll
    for (int i = tid; i < Dm; i += 256) {
        float y = (xs[i] - mu) * inv * g[i] + bb[i];
        op[i]  = y;
        opr[i] = tf32r(y);
    }
}

// ---------------------------------------------------------------------------
// mma.sync m16n8k8 tf32 helper
// ---------------------------------------------------------------------------
__device__ __forceinline__ void mma_tf32(float* c, uint32_t a0, uint32_t a1,
                                         uint32_t a2, uint32_t a3,
                                         uint32_t b0, uint32_t b1)
{
    asm volatile(
        "mma.sync.aligned.m16n8k8.row.col.f32.tf32.tf32.f32 "
        "{%0,%1,%2,%3}, {%4,%5,%6,%7}, {%8,%9}, {%0,%1,%2,%3};"
        : "+f"(c[0]), "+f"(c[1]), "+f"(c[2]), "+f"(c[3])
        : "r"(a0), "r"(a1), "r"(a2), "r"(a3), "r"(b0), "r"(b1));
}

// ---------------------------------------------------------------------------
// Tensor-core GEMM with 2-stage cp.async pipeline.
// Inputs A and W are PRE-ROUNDED to tf32 (producer-side), so the k-loop is
// pure copy + mma. C = A @ W + bias (+residual) (+GELU, stored tf32-rounded).
// 128x128x32 block tile, 8 warps, warp tile 64x32.
// ---------------------------------------------------------------------------
#define ASTR 40
#define BSTR 136
#define SA (128*ASTR)   // 5120 floats per A stage
#define SB (32*BSTR)    // 4352 floats per B stage
#define GEMM_SMEM (2*(SA+SB)*4)

extern __shared__ float smem_dyn[];

template<bool RES, bool GELU>
__global__ void __launch_bounds__(256, 2)
gemm_tc(const float* __restrict__ A, const float* __restrict__ W,
        const float* __restrict__ bias, const float* __restrict__ Rsrc,
        float* __restrict__ C, int M, int N, int K)
{
    float* As = smem_dyn;
    float* Bs = smem_dyn + 2*SA;

    int tid = threadIdx.x, lane = tid & 31, warp = tid >> 5;
    int wm = warp >> 2, wn = warp & 3;
    int bm = blockIdx.y * 128, bn = blockIdx.x * 128;
    int g = lane >> 2, t4 = lane & 3;
    int swz = (g & 4);
    int ntiles = K >> 5;

    auto issue = [&](int tile, int st) {
        int k0 = tile * 32;
        float* Ad = As + st * SA;
        float* Bd = Bs + st * SB;
        #pragma unroll
        for (int it = 0; it < 4; it++) {
            int idx = tid + it * 256;
            int r = idx >> 3, c = (idx & 7) << 2;
            uint32_t d = (uint32_t)__cvta_generic_to_shared(Ad + r * ASTR + (c ^ (r & 4)));
            const float* s = A + (size_t)(bm + r) * K + k0 + c;
            asm volatile("cp.async.cg.shared.global [%0], [%1], 16;" :: "r"(d), "l"(s));
        }
        #pragma unroll
        for (int it = 0; it < 4; it++) {
            int idx = tid + it * 256;
            int r = idx >> 5, c = (idx & 31) << 2;
            uint32_t d = (uint32_t)__cvta_generic_to_shared(Bd + r * BSTR + c);
            const float* s = W + (size_t)(k0 + r) * N + bn + c;
            asm volatile("cp.async.cg.shared.global [%0], [%1], 16;" :: "r"(d), "l"(s));
        }
    };

    float acc[4][4][4];
    #pragma unroll
    for (int i = 0; i < 4; i++)
        #pragma unroll
        for (int j = 0; j < 4; j++)
            #pragma unroll
            for (int c = 0; c < 4; c++) acc[i][j][c] = 0.f;

    issue(0, 0);
    asm volatile("cp.async.commit_group;");

    for (int t = 0; t < ntiles; t++) {
        if (t + 1 < ntiles) {
            issue(t + 1, (t + 1) & 1);
            asm volatile("cp.async.commit_group;");
            asm volatile("cp.async.wait_group 1;");
        } else {
            asm volatile("cp.async.wait_group 0;");
        }
        __syncthreads();

        const float* Ast = As + (t & 1) * SA;
        const float* Bst = Bs + (t & 1) * SB;

        #pragma unroll
        for (int ks = 0; ks < 4; ks++) {
            int kb = ks * 8;
            int kA  = (kb + t4) ^ swz;
            int kA4 = (kb + t4 + 4) ^ swz;
            uint32_t a[4][4], b[4][2];
            #pragma unroll
            for (int mt = 0; mt < 4; mt++) {
                int r0 = wm * 64 + mt * 16 + g;
                int r1 = r0 + 8;
                a[mt][0] = __float_as_uint(Ast[r0 * ASTR + kA ]);
                a[mt][1] = __float_as_uint(Ast[r1 * ASTR + kA ]);
                a[mt][2] = __float_as_uint(Ast[r0 * ASTR + kA4]);
                a[mt][3] = __float_as_uint(Ast[r1 * ASTR + kA4]);
            }
            #pragma unroll
            for (int nt = 0; nt < 4; nt++) {
                int col = wn * 32 + nt * 8 + g;
                b[nt][0] = __float_as_uint(Bst[(kb + t4    ) * BSTR + col]);
                b[nt][1] = __float_as_uint(Bst[(kb + t4 + 4) * BSTR + col]);
            }
            #pragma unroll
            for (int mt = 0; mt < 4; mt++)
                #pragma unroll
                for (int nt = 0; nt < 4; nt++)
                    mma_tf32(acc[mt][nt], a[mt][0], a[mt][1], a[mt][2], a[mt][3],
                             b[nt][0], b[nt][1]);
        }
        __syncthreads();
    }

    #pragma unroll
    for (int mt = 0; mt < 4; mt++) {
        #pragma unroll
        for (int nt = 0; nt < 4; nt++) {
            int col = bn + wn * 32 + nt * 8 + t4 * 2;
            float b0 = bias[col], b1 = bias[col + 1];
            #pragma unroll
            for (int half = 0; half < 2; half++) {
                int row = bm + wm * 64 + mt * 16 + g + half * 8;
                float v0 = acc[mt][nt][half * 2 + 0] + b0;
                float v1 = acc[mt][nt][half * 2 + 1] + b1;
                if (RES) {
                    v0 += Rsrc[(size_t)row * N + col];
                    v1 += Rsrc[(size_t)row * N + col + 1];
                }
                if (GELU) {
                    // GELU output feeds the next GEMM's A input only -> store rounded
                    v0 = tf32r(gelu_f(v0)); v1 = tf32r(gelu_f(v1));
                }
                *(float2*)(C + (size_t)row * N + col) = make_float2(v0, v1);
            }
        }
    }
}

// ---------------------------------------------------------------------------
// Tensor-core flash attention (as R11), but ctx is stored tf32-rounded
// (it feeds only the out-projection GEMM's A input).
// ---------------------------------------------------------------------------
#define KSTR 68
#define VSTR 72
#define PSTR 36

template<bool CAUSAL>
__global__ void __launch_bounds__(128)
attn_tc(const float* __restrict__ Qp, const float* __restrict__ Kp,
        const float* __restrict__ Vp, const int* __restrict__ ids,
        float* __restrict__ O)
{
    __shared__ float Qs[64 * KSTR];
    __shared__ float Ks[32 * KSTR];
    __shared__ float Vs[32 * VSTR];
    __shared__ float Ps[64 * PSTR];
    __shared__ int   ids_s[32];

    int b = blockIdx.z, h = blockIdx.y, qb = blockIdx.x;
    int tid = threadIdx.x, lane = tid & 31, warp = tid >> 5;
    int g = lane >> 2, t4 = lane & 3;

    #pragma unroll
    for (int i = tid; i < 64 * 16; i += 128) {
        int r = i >> 4, c4 = (i & 15) << 2;
        size_t base = (((size_t)b * Sm + qb * 64 + r) * Hh + h) * DHh + c4;
        float4 v = *(const float4*)(Qp + base);
        Qs[r*KSTR + c4+0] = tf32r(v.x) * 0.125f;
        Qs[r*KSTR + c4+1] = tf32r(v.y) * 0.125f;
        Qs[r*KSTR + c4+2] = tf32r(v.z) * 0.125f;
        Qs[r*KSTR + c4+3] = tf32r(v.w) * 0.125f;
    }
    __syncthreads();

    uint32_t qa[8][4];
    int rw0 = warp * 16 + g, rw1 = rw0 + 8;
    #pragma unroll
    for (int kc = 0; kc < 8; kc++) {
        qa[kc][0] = __float_as_uint(Qs[rw0*KSTR + kc*8 + t4    ]);
        qa[kc][1] = __float_as_uint(Qs[rw1*KSTR + kc*8 + t4    ]);
        qa[kc][2] = __float_as_uint(Qs[rw0*KSTR + kc*8 + t4 + 4]);
        qa[kc][3] = __float_as_uint(Qs[rw1*KSTR + kc*8 + t4 + 4]);
    }

    float m0 = -1e30f, m1 = -1e30f, l0 = 0.f, l1 = 0.f;
    float o[8][4];
    #pragma unroll
    for (int nt = 0; nt < 8; nt++)
        #pragma unroll
        for (int c = 0; c < 4; c++) o[nt][c] = 0.f;

    int qrow0 = qb * 64 + warp * 16 + g;
    int qrow1 = qrow0 + 8;
    int ktiles = CAUSAL ? (qb * 2 + 2) : (Sm / 32);

    for (int kt = 0; kt < ktiles; kt++) {
        int k0 = kt * 32;
        __syncthreads();
        #pragma unroll
        for (int i = tid; i < 32 * 16; i += 128) {
            int r = i >> 4, c4 = (i & 15) << 2;
            size_t base = (((size_t)b * Sm + k0 + r) * Hh + h) * DHh + c4;
            float4 vk = *(const float4*)(Kp + base);
            Ks[r*KSTR + c4+0] = tf32r(vk.x); Ks[r*KSTR + c4+1] = tf32r(vk.y);
            Ks[r*KSTR + c4+2] = tf32r(vk.z); Ks[r*KSTR + c4+3] = tf32r(vk.w);
            float4 vv = *(const float4*)(Vp + base);
            Vs[r*VSTR + c4+0] = tf32r(vv.x); Vs[r*VSTR + c4+1] = tf32r(vv.y);
            Vs[r*VSTR + c4+2] = tf32r(vv.z); Vs[r*VSTR + c4+3] = tf32r(vv.w);
        }
        if (tid < 32) ids_s[tid] = ids[b * Sm + k0 + tid];
        __syncthreads();

        float s[4][4];
        #pragma unroll
        for (int nt = 0; nt < 4; nt++) {
            s[nt][0] = s[nt][1] = s[nt][2] = s[nt][3] = 0.f;
            const float* kb = &Ks[(nt*8 + g) * KSTR];
            #pragma unroll
            for (int kc = 0; kc < 8; kc++) {
                uint32_t b0 = __float_as_uint(kb[kc*8 + t4    ]);
                uint32_t b1 = __float_as_uint(kb[kc*8 + t4 + 4]);
                mma_tf32(s[nt], qa[kc][0], qa[kc][1], qa[kc][2], qa[kc][3], b0, b1);
            }
        }

        bool diag = CAUSAL && (k0 + 31 > qb * 64);
        #pragma unroll
        for (int nt = 0; nt < 4; nt++) {
            int lk0 = nt*8 + 2*t4, lk1 = lk0 + 1;
            float pad0 = (ids_s[lk0] == 0) ? NEGM : 0.f;
            float pad1 = (ids_s[lk1] == 0) ? NEGM : 0.f;
            s[nt][0] += pad0; s[nt][1] += pad1;
            s[nt][2] += pad0; s[nt][3] += pad1;
            if (diag) {
                int key0 = k0 + lk0, key1 = k0 + lk1;
                if (key0 > qrow0) s[nt][0] += NEGM;
                if (key1 > qrow0) s[nt][1] += NEGM;
                if (key0 > qrow1) s[nt][2] += NEGM;
                if (key1 > qrow1) s[nt][3] += NEGM;
            }
        }

        float tm0 = -1e30f, tm1 = -1e30f;
        #pragma unroll
        for (int nt = 0; nt < 4; nt++) {
            tm0 = fmaxf(tm0, fmaxf(s[nt][0], s[nt][1]));
            tm1 = fmaxf(tm1, fmaxf(s[nt][2], s[nt][3]));
        }
        tm0 = fmaxf(tm0, __shfl_xor_sync(0xffffffffu, tm0, 1));
        tm0 = fmaxf(tm0, __shfl_xor_sync(0xffffffffu, tm0, 2));
        tm1 = fmaxf(tm1, __shfl_xor_sync(0xffffffffu, tm1, 1));
        tm1 = fmaxf(tm1, __shfl_xor_sync(0xffffffffu, tm1, 2));

        float mn0 = fmaxf(m0, tm0), mn1 = fmaxf(m1, tm1);
        float cr0 = expf(m0 - mn0), cr1 = expf(m1 - mn1);
        l0 *= cr0; l1 *= cr1;
        #pragma unroll
        for (int nt = 0; nt < 8; nt++) {
            o[nt][0] *= cr0; o[nt][1] *= cr0;
            o[nt][2] *= cr1; o[nt][3] *= cr1;
        }

        float ps0 = 0.f, ps1 = 0.f;
        #pragma unroll
        for (int nt = 0; nt < 4; nt++) {
            float p0 = expf(s[nt][0] - mn0);
            float p1 = expf(s[nt][1] - mn0);
            float p2 = expf(s[nt][2] - mn1);
            float p3 = expf(s[nt][3] - mn1);
            ps0 += p0 + p1; ps1 += p2 + p3;
            *(float2*)&Ps[rw0*PSTR + nt*8 + 2*t4] = make_float2(tf32r(p0), tf32r(p1));
            *(float2*)&Ps[rw1*PSTR + nt*8 + 2*t4] = make_float2(tf32r(p2), tf32r(p3));
        }
        ps0 += __shfl_xor_sync(0xffffffffu, ps0, 1);
        ps0 += __shfl_xor_sync(0xffffffffu, ps0, 2);
        ps1 += __shfl_xor_sync(0xffffffffu, ps1, 1);
        ps1 += __shfl_xor_sync(0xffffffffu, ps1, 2);
        l0 += ps0; l1 += ps1;
        m0 = mn0; m1 = mn1;
        __syncwarp();

        #pragma unroll
        for (int kc = 0; kc < 4; kc++) {
            uint32_t a0 = __float_as_uint(Ps[rw0*PSTR + kc*8 + t4    ]);
            uint32_t a1 = __float_as_uint(Ps[rw1*PSTR + kc*8 + t4    ]);
            uint32_t a2 = __float_as_uint(Ps[rw0*PSTR + kc*8 + t4 + 4]);
            uint32_t a3 = __float_as_uint(Ps[rw1*PSTR + kc*8 + t4 + 4]);
            const float* v0p = &Vs[(kc*8 + t4    ) * VSTR];
            const float* v1p = &Vs[(kc*8 + t4 + 4) * VSTR];
            #pragma unroll
            for (int nt = 0; nt < 8; nt++) {
                uint32_t b0 = __float_as_uint(v0p[nt*8 + g]);
                uint32_t b1 = __float_as_uint(v1p[nt*8 + g]);
                mma_tf32(o[nt], a0, a1, a2, a3, b0, b1);
            }
        }
    }

    // ctx feeds only the out-projection GEMM A input -> store tf32-rounded
    float i0 = 1.0f / l0, i1 = 1.0f / l1;
    size_t ob0 = (((size_t)b * Sm + qrow0) * Hh + h) * DHh;
    size_t ob1 = (((size_t)b * Sm + qrow1) * Hh + h) * DHh;
    #pragma unroll
    for (int nt = 0; nt < 8; nt++) {
        int col = nt*8 + 2*t4;
        *(float2*)(O + ob0 + col) = make_float2(tf32r(o[nt][0] * i0), tf32r(o[nt][1] * i0));
        *(float2*)(O + ob1 + col) = make_float2(tf32r(o[nt][2] * i1), tf32r(o[nt][3] * i1));
    }
}

// ---------------------------------------------------------------------------
// Launch
// ---------------------------------------------------------------------------
extern "C" void kernel_launch(void* const* d_in, const int* in_sizes, int n_in,
                              void* d_out, int out_size)
{
    const float* input_embedding = (const float*)d_in[0];
    const int*   input_ids       = (const int*)  d_in[1];
    const int*   target_ids      = (const int*)  d_in[2];
    const float* tok_emb = (const float*)d_in[3];
    const float* pos_emb = (const float*)d_in[4];
    const float* ln1_g = (const float*)d_in[5],  *ln1_b = (const float*)d_in[6];
    const float* q1_w  = (const float*)d_in[7],  *q1_b  = (const float*)d_in[8];
    const float* k1_w  = (const float*)d_in[9],  *k1_b  = (const float*)d_in[10];
    const float* v1_w  = (const float*)d_in[11], *v1_b  = (const float*)d_in[12];
    const float* out1_w= (const float*)d_in[13], *out1_b= (const float*)d_in[14];
    const float* ln2_g = (const float*)d_in[15], *ln2_b = (const float*)d_in[16];
    const float* q2_w  = (const float*)d_in[17], *q2_b  = (const float*)d_in[18];
    const float* k2_w  = (const float*)d_in[19], *k2_b  = (const float*)d_in[20];
    const float* v2_w  = (const float*)d_in[21], *v2_b  = (const float*)d_in[22];
    const float* out2_w= (const float*)d_in[23], *out2_b= (const float*)d_in[24];
    const float* ln3_g = (const float*)d_in[25], *ln3_b = (const float*)d_in[26];
    const float* mlp_w1= (const float*)d_in[27], *mlp_b1= (const float*)d_in[28];
    const float* mlp_w2= (const float*)d_in[29], *mlp_b2= (const float*)d_in[30];
    float* out = (float*)d_out;

    float *xln,*xlnr,*q,*k,*v,*ctx,*h,*hln,*hlnr,*r,*z,*zr,*mlp,*wr,*ier;
    cudaGetSymbolAddress((void**)&xln,  g_xln);
    cudaGetSymbolAddress((void**)&xlnr, g_xlnr);
    cudaGetSymbolAddress((void**)&q,    g_q);
    cudaGetSymbolAddress((void**)&k,    g_k);
    cudaGetSymbolAddress((void**)&v,    g_v);
    cudaGetSymbolAddress((void**)&ctx,  g_ctx);
    cudaGetSymbolAddress((void**)&h,    g_h);
    cudaGetSymbolAddress((void**)&hln,  g_hln);
    cudaGetSymbolAddress((void**)&hlnr, g_hlnr);
    cudaGetSymbolAddress((void**)&r,    g_r);
    cudaGetSymbolAddress((void**)&z,    g_z);
    cudaGetSymbolAddress((void**)&zr,   g_zr);
    cudaGetSymbolAddress((void**)&mlp,  g_mlp);
    cudaGetSymbolAddress((void**)&wr,   g_wr);
    cudaGetSymbolAddress((void**)&ier,  g_ier);

    // Opt-in to 74KB dynamic smem for the pipelined GEMM (idempotent).
    cudaFuncSetAttribute(gemm_tc<false,false>, cudaFuncAttributeMaxDynamicSharedMemorySize, GEMM_SMEM);
    cudaFuncSetAttribute(gemm_tc<true ,false>, cudaFuncAttributeMaxDynamicSharedMemorySize, GEMM_SMEM);
    cudaFuncSetAttribute(gemm_tc<false,true >, cudaFuncAttributeMaxDynamicSharedMemorySize, GEMM_SMEM);

    // Pre-round weights + encoder states to TF32 (producer-side rounding).
    const int M1 = 1024*1024;
    round_copy<<<M1/1024, 256>>>(q1_w,  wr + W_Q1, M1/4);
    round_copy<<<M1/1024, 256>>>(k1_w,  wr + W_K1, M1/4);
    round_copy<<<M1/1024, 256>>>(v1_w,  wr + W_V1, M1/4);
    round_copy<<<M1/1024, 256>>>(out1_w,wr + W_O1, M1/4);
    round_copy<<<M1/1024, 256>>>(q2_w,  wr + W_Q2, M1/4);
    round_copy<<<M1/1024, 256>>>(k2_w,  wr + W_K2, M1/4);
    round_copy<<<M1/1024, 256>>>(v2_w,  wr + W_V2, M1/4);
    round_copy<<<M1/1024, 256>>>(out2_w,wr + W_O2, M1/4);
    round_copy<<<4*M1/1024, 256>>>(mlp_w1, wr + W_M1, M1);
    round_copy<<<4*M1/1024, 256>>>(mlp_w2, wr + W_M2, M1);
    round_copy<<<ROWS*Dm/1024, 256>>>(input_embedding, ier, ROWS*Dm/4);

    dim3 gP(Dm / 128, ROWS / 128);      // projections: N=1024
    dim3 gU(4 * Dm / 128, ROWS / 128);  // MLP up: N=4096
    dim3 gA(Sm / 64, Hh, Bm);           // attention: 64 q rows per block

    // x = LN1(tok_emb[target_ids] + pos_emb); xln full, xlnr rounded
    embed_ln_kernel<<<ROWS, 256>>>(target_ids, tok_emb, pos_emb, ln1_g, ln1_b, xln, xlnr);

    // Self-attention QKV
    gemm_tc<false,false><<<gP, 256, GEMM_SMEM>>>(xlnr, wr + W_Q1, q1_b, nullptr, q, ROWS, Dm, Dm);
    gemm_tc<false,false><<<gP, 256, GEMM_SMEM>>>(xlnr, wr + W_K1, k1_b, nullptr, k, ROWS, Dm, Dm);
    gemm_tc<false,false><<<gP, 256, GEMM_SMEM>>>(xlnr, wr + W_V1, v1_b, nullptr, v, ROWS, Dm, Dm);
    attn_tc<true><<<gA, 128>>>(q, k, v, target_ids, ctx);
    // h = xln + ctx @ out1_w + out1_b
    gemm_tc<true,false><<<gP, 256, GEMM_SMEM>>>(ctx, wr + W_O1, out1_b, xln, h, ROWS, Dm, Dm);

    // Cross-attention. Reference reassigns h = LN2(h); residual is hln.
    ln_kernel<<<ROWS, 256>>>(h, ln2_g, ln2_b, hln, hlnr);
    gemm_tc<false,false><<<gP, 256, GEMM_SMEM>>>(hlnr, wr + W_Q2, q2_b, nullptr, q, ROWS, Dm, Dm);
    gemm_tc<false,false><<<gP, 256, GEMM_SMEM>>>(ier,  wr + W_K2, k2_b, nullptr, k, ROWS, Dm, Dm);
    gemm_tc<false,false><<<gP, 256, GEMM_SMEM>>>(ier,  wr + W_V2, v2_b, nullptr, v, ROWS, Dm, Dm);
    attn_tc<false><<<gA, 128>>>(q, k, v, input_ids, ctx);
    // r = LN2(h) + ctx @ out2_w + out2_b
    gemm_tc<true,false><<<gP, 256, GEMM_SMEM>>>(ctx, wr + W_O2, out2_b, hln, r, ROWS, Dm, Dm);

    // MLP
    ln_kernel<<<ROWS, 256>>>(r, ln3_g, ln3_b, z, zr);
    gemm_tc<false,true><<<gU, 256, GEMM_SMEM>>>(zr, wr + W_M1, mlp_b1, nullptr, mlp, ROWS, 4 * Dm, Dm);
    gemm_tc<true,false><<<gP, 256, GEMM_SMEM>>>(mlp, wr + W_M2, mlp_b2, r, out, ROWS, Dm, 4 * Dm);
}